// round 9
// baseline (speedup 1.0000x reference)
#include <cuda_runtime.h>
#include <cuda_bf16.h>
#include <math.h>

// ChainCRF: B=128, S=256, C=64.
// FOUR WARPS per batch row (128 CTAs x 128 threads).
// Thread tau: column j = tau>>1, half h = tau&1 (i-range [32h, 32h+32)).
// Linear-domain forward recursion; power-of-two renorm folded into the
// exp'd emission multiplier (off-chain); log taken once at the end.
// Per step per thread: 8 broadcast LDS.128, 16 fma.rn.f32x2, shfl.bfly(1)
// combine with the same-warp partner, predicated STS, one __syncthreads.

#define Bc 128
#define Sc 256
#define Cc 64
#define Tc 128

__device__ float g_batch_res[Bc];
__device__ unsigned int g_ticket = 0;

#define FMA2(d,a,b,c)  asm("fma.rn.f32x2 %0, %1, %2, %3;" : "=l"(d) : "l"(a), "l"(b), "l"(c))
#define ADD2(d,a,b)    asm("add.rn.f32x2 %0, %1, %2;" : "=l"(d) : "l"(a), "l"(b))
#define PACK2(d,lo,hi) asm("mov.b64 %0, {%1, %2};" : "=l"(d) : "f"(lo), "f"(hi))
#define UNPACK2(lo,hi,s) asm("mov.b64 {%0, %1}, %2;" : "=f"(lo), "=f"(hi) : "l"(s))

// One step: q_new[j] = (sum_i q_i * expU[i][j]) * emx_j * scale.
// This thread does i in [32h,32h+32); partner (tau^1) does the other half.
#define STEP(QR, QW, EMX) do {                                                 \
    float _q0 = (QR)[0];                                                       \
    int   _k  = (int)((__float_as_uint(_q0) >> 23) & 0xFF) - 127;              \
    K += _k;                                                                   \
    float _emx = (EMX) * __uint_as_float((unsigned)(127 - _k) << 23);          \
    unsigned long long _a0 = 0ull, _a1 = 0ull;                                 \
    const ulonglong2* _qv = (const ulonglong2*)((QR) + hbase);                 \
    _Pragma("unroll")                                                          \
    for (int _c = 0; _c < 8; ++_c) {                                           \
        ulonglong2 _v = _qv[_c];                                               \
        FMA2(_a0, _v.x, rE[2*_c+0], _a0);                                      \
        FMA2(_a1, _v.y, rE[2*_c+1], _a1);                                      \
    }                                                                          \
    ADD2(_a0, _a0, _a1);                                                       \
    float _lo, _hi;                                                            \
    UNPACK2(_lo, _hi, _a0);                                                    \
    float _sh = _lo + _hi;                                                     \
    float _so = __shfl_xor_sync(0xFFFFFFFFu, _sh, 1);                          \
    if (h == 0) (QW)[j] = (_sh + _so) * _emx;                                  \
    __syncthreads();                                                           \
} while (0)

__global__ __launch_bounds__(Tc, 1)
void crf_kernel(const float* __restrict__ em,
                const int*   __restrict__ tags,
                const float* __restrict__ mask,
                const float* __restrict__ U,
                float* __restrict__ out)
{
    const int b   = blockIdx.x;
    const int tau = threadIdx.x;         // 0..127
    const int j   = tau >> 1;            // column (0..63)
    const int h   = tau & 1;             // i-half
    const int l   = tau & 31;            // lane
    const int w   = tau >> 5;            // warp (0..3)
    const int hbase = 32 * h;

    __shared__ __align__(16) float qA[Cc];
    __shared__ __align__(16) float qB[Cc];
    __shared__ __align__(16) float sU[Cc * Cc];
    __shared__ __align__(16) int   stags[Sc];
    __shared__ __align__(16) float smask[Sc];
    __shared__ float red[4];

    // ---- stage U, tags, mask into smem (coalesced) ----
    {
        const float4* U4  = (const float4*)U;
        float4*       sU4 = (float4*)sU;
#pragma unroll
        for (int i = 0; i < (Cc * Cc / 4) / Tc; ++i)     // 8 iters
            sU4[tau + Tc * i] = U4[tau + Tc * i];

        if (tau < 64) {
            ((int4*)stags)[tau]  = ((const int4*)(tags + (size_t)b * Sc))[tau];
            ((float4*)smask)[tau] = ((const float4*)(mask + (size_t)b * Sc))[tau];
        }
    }
    __syncthreads();

    // ---- expU half-column: 16 u64 packed over i-pairs in [32h, 32h+32) ----
    unsigned long long rE[16];
#pragma unroll
    for (int p = 0; p < 16; ++p) {
        float e0 = __expf(sU[(hbase + 2 * p + 0) * Cc + j]);
        float e1 = __expf(sU[(hbase + 2 * p + 1) * Cc + j]);
        PACK2(rE[p], e0, e1);            // {E[hb+2p][j], E[hb+2p+1][j]}
    }

    const float* emb = em + (size_t)b * Sc * Cc;   // em[t][j] = emb[t*64 + j]

    // mask uniformity check (hoists the branch out of the hot loop)
    int ok = 1;
#pragma unroll
    for (int t = tau; t < Sc; t += Tc) ok &= (smask[t] == 1.0f);
    ok = __syncthreads_and(ok);

    // q(0) = exp(em[0])
    if (h == 0) qA[j] = __expf(emb[j]);
    int K = 0;
    __syncthreads();

    if (ok) {
        // ---- fast path: branch-free, deep prefetch (distance 4..7) ----
        float r1 = emb[1 * Cc + j];
        float c2 = emb[2 * Cc + j], c3 = emb[3 * Cc + j];
        float c4 = emb[4 * Cc + j], c5 = emb[5 * Cc + j];
        float c6 = emb[6 * Cc + j], c7 = emb[7 * Cc + j];

        float ex1  = __expf(r1);         // for t=1
        float ex0n = __expf(c2);         // for t=2
        float ex1n = __expf(c3);         // for t=3

        STEP(qA, qB, ex1);               // t = 1

        float ex0 = ex0n, exo = ex1n;
        c2 = c4; c3 = c5; c4 = c6; c5 = c7;   // raw for t+2..t+5 at t=2

#pragma unroll 1
        for (int t = 2; t < Sc; t += 2) {
            float n6 = (t + 6 < Sc) ? emb[(t + 6) * Cc + j] : 0.0f;
            float n7 = (t + 7 < Sc) ? emb[(t + 7) * Cc + j] : 0.0f;
            float exa = __expf(c2);      // for t+2
            float exb = __expf(c3);      // for t+3

            STEP(qB, qA, ex0);           // step t   (even)
            STEP(qA, qB, exo);           // step t+1 (odd)

            ex0 = exa; exo = exb;
            c2 = c4; c3 = c5; c4 = n6; c5 = n7;
        }
        // t=255 (odd) wrote qB
    } else {
        // ---- generic masked fallback (never taken in this dataset) ----
        const float* qr = qA; float* qw = qB;
        for (int t = 1; t < Sc; ++t) {
            float m   = smask[t];
            float emv = emb[t * Cc + j];
            float q0  = qr[0];
            int   k   = (int)((__float_as_uint(q0) >> 23) & 0xFF) - 127;
            float sc  = __uint_as_float((unsigned)(127 - k) << 23);
            K += k;

            if (h == 0) {
                float s;
                if (m == 1.0f) {
                    float a = 0.f;
                    for (int i = 0; i < Cc; ++i)
                        a = fmaf(qr[i], __expf(sU[i * Cc + j]), a);
                    s = a * __expf(emv);
                } else if (m == 0.0f) {
                    float a = 0.f;
                    for (int i = 0; i < Cc; ++i) a += qr[i];
                    s = a;
                } else {
                    float a = 0.f;
                    for (int i = 0; i < Cc; ++i)
                        a += qr[i] * __expf((emv + sU[i * Cc + j]) * m);
                    s = a;
                }
                qw[j] = s * sc;
            }
            __syncthreads();
            const float* tr = qr; qr = qw; qw = const_cast<float*>(tr);
        }
        // t=255 (odd) wrote qB
    }

    // ---- path energy ----
    float pe = 0.0f;
#pragma unroll
    for (int t = tau; t < Sc; t += Tc) {
        float mt = smask[t];
        int   tg = stags[t];
        int   tm = (int)((float)tg * mt);
        pe += emb[t * Cc + tm] * mt;
    }
#pragma unroll
    for (int t = 1 + tau; t < Sc; t += Tc) {
        pe += sU[stags[t - 1] * Cc + stags[t]] * smask[t];
    }
#pragma unroll
    for (int o = 16; o > 0; o >>= 1)
        pe += __shfl_xor_sync(0xFFFFFFFFu, pe, o);
    if (l == 0) red[w] = pe;
    __syncthreads();

    // ---- free energy + per-batch result + fused finalize ----
    if (tau == 0) {
        float qs = 0.0f;
#pragma unroll
        for (int i = 0; i < Cc; ++i) qs += qB[i];
        float fe = logf(qs) + (float)K * 0.6931471805599453f;
        g_batch_res[b] = fe - (red[0] + red[1] + red[2] + red[3]);
        __threadfence();
    }
    __syncthreads();

    if (w == 0) {
        unsigned int old = 0;
        if (l == 0) old = atomicAdd(&g_ticket, 1u);
        old = __shfl_sync(0xFFFFFFFFu, old, 0);
        if (old == Bc - 1) {
            __threadfence();
            float v = 0.0f;
#pragma unroll
            for (int i = 0; i < Bc / 32; ++i) v += g_batch_res[l + 32 * i];
#pragma unroll
            for (int o = 16; o > 0; o >>= 1)
                v += __shfl_xor_sync(0xFFFFFFFFu, v, o);
            if (l == 0) {
                out[0] = v * (1.0f / (float)Bc);
                g_ticket = 0;              // reset for next graph replay
            }
        }
    }
}

extern "C" void kernel_launch(void* const* d_in, const int* in_sizes, int n_in,
                              void* d_out, int out_size)
{
    const float* emissions = (const float*)d_in[0];
    const int*   true_tags = (const int*)  d_in[1];
    const float* mask      = (const float*)d_in[2];
    const float* U         = (const float*)d_in[3];
    float* out = (float*)d_out;

    crf_kernel<<<Bc, Tc>>>(emissions, true_tags, mask, U, out);
}